// round 7
// baseline (speedup 1.0000x reference)
#include <cuda_runtime.h>
#include <cuda_fp16.h>

#define N_NODES   50000
#define N_EDGES   800000
#define F_IN      16
#define F_EDGE    8
#define H         8
#define NUM_GRAPHS 512

#define SCAN_TPB  512
#define SCAN_BLKS ((N_NODES + SCAN_TPB - 1) / SCAN_TPB)   // 98

// Q (o-major, fp16): Q[n][j*8+f], row = 64 halves = 128 B, line-aligned.
__device__ __align__(128) __half g_Qh[N_NODES * 64];       // 6.4 MB
__device__ __align__(16)  float  g_bias[N_NODES * H];      // 1.6 MB
__device__ __align__(16)  float  g_agg1[N_NODES * H];      // 1.6 MB
__device__ __align__(16)  float  g_agg2[N_NODES * H];      // 1.6 MB

// CSR build scratch
__device__ int g_cnt[N_NODES];
__device__ int g_rowptr[N_NODES + 1];
__device__ int g_cursor[N_NODES];
__device__ int g_blksum[SCAN_BLKS];
__device__ int g_src_sorted[N_EDGES];                      // 3.2 MB
__device__ __align__(16) __half g_ea16[N_EDGES * 8];       // 12.8 MB

// ---------------------------------------------------------------------------
// CSR build: zero -> histogram(dst) -> exclusive scan -> scatter permute
// ---------------------------------------------------------------------------
__global__ void zero_cnt_kernel() {
    int i = blockIdx.x * blockDim.x + threadIdx.x;
    if (i < N_NODES) g_cnt[i] = 0;
}

__global__ void hist_kernel(const int* __restrict__ ei) {
    int e = blockIdx.x * blockDim.x + threadIdx.x;
    if (e < N_EDGES) atomicAdd(&g_cnt[__ldg(&ei[N_EDGES + e])], 1);
}

__global__ void scan1_kernel() {
    __shared__ int sh[SCAN_TPB];
    int tid = threadIdx.x;
    int i = blockIdx.x * SCAN_TPB + tid;
    int v = (i < N_NODES) ? g_cnt[i] : 0;
    sh[tid] = v;
    __syncthreads();
    #pragma unroll
    for (int off = 1; off < SCAN_TPB; off <<= 1) {
        int t = (tid >= off) ? sh[tid - off] : 0;
        __syncthreads();
        sh[tid] += t;
        __syncthreads();
    }
    if (i < N_NODES) g_rowptr[i] = sh[tid] - v;   // block-local exclusive
    if (tid == SCAN_TPB - 1) g_blksum[blockIdx.x] = sh[tid];
}

__global__ void scan2_kernel() {
    __shared__ int sh[128];
    int tid = threadIdx.x;
    int v = (tid < SCAN_BLKS) ? g_blksum[tid] : 0;
    sh[tid] = v;
    __syncthreads();
    #pragma unroll
    for (int off = 1; off < 128; off <<= 1) {
        int t = (tid >= off) ? sh[tid - off] : 0;
        __syncthreads();
        sh[tid] += t;
        __syncthreads();
    }
    if (tid < SCAN_BLKS) g_blksum[tid] = sh[tid] - v;  // exclusive block offsets
}

__global__ void scan3_kernel() {
    int i = blockIdx.x * blockDim.x + threadIdx.x;
    if (i < N_NODES) {
        int r = g_rowptr[i] + g_blksum[i / SCAN_TPB];
        g_rowptr[i] = r;
        g_cursor[i] = r;
    }
    if (i == 0) g_rowptr[N_NODES] = N_EDGES;
}

__global__ void scatter_kernel(const int* __restrict__ ei,
                               const float* __restrict__ ea) {
    int e = blockIdx.x * blockDim.x + threadIdx.x;
    if (e >= N_EDGES) return;
    int s = __ldg(&ei[e]);
    int d = __ldg(&ei[N_EDGES + e]);
    int pos = atomicAdd(&g_cursor[d], 1);
    g_src_sorted[pos] = s;
    const float4* eap = (const float4*)(ea + e * 8);
    float4 a0 = __ldg(eap);
    float4 a1 = __ldg(eap + 1);
    union { uint4 u; __half2 h[4]; } pk;
    pk.h[0] = __floats2half2_rn(a0.x, a0.y);
    pk.h[1] = __floats2half2_rn(a0.z, a0.w);
    pk.h[2] = __floats2half2_rn(a1.x, a1.y);
    pk.h[3] = __floats2half2_rn(a1.z, a1.w);
    *(uint4*)(g_ea16 + (size_t)pos * 8) = pk.u;
}

// ---------------------------------------------------------------------------
// Layer-1 node precompute (8 lanes per node, lane j = output channel j):
//   Qh[n][j*8+f] = sum_i x[n,i]*We1[f, i*8+j]    (fp16, o-major)
//   bias[n][j]   = sum_i x[n,i]*be1[i*8+j]
//   agg1[n][j]   = x[n]@root1[:,j] + b1[j]       (init term)
// ---------------------------------------------------------------------------
__global__ void node1_kernel(const float* __restrict__ x,
                             const float* __restrict__ We1,
                             const float* __restrict__ be1,
                             const float* __restrict__ root1,
                             const float* __restrict__ b1) {
    __shared__ float sW[F_EDGE * F_IN * H];
    __shared__ float sR[F_IN * H];
    __shared__ float sB[F_IN * H];
    __shared__ float sb[H];
    for (int i = threadIdx.x; i < F_EDGE * F_IN * H; i += blockDim.x) sW[i] = We1[i];
    for (int i = threadIdx.x; i < F_IN * H; i += blockDim.x) { sR[i] = root1[i]; sB[i] = be1[i]; }
    if (threadIdx.x < H) sb[threadIdx.x] = b1[threadIdx.x];
    __syncthreads();

    int gid = blockIdx.x * blockDim.x + threadIdx.x;
    int n = gid >> 3, j = gid & 7;
    if (n >= N_NODES) return;

    float xv[F_IN];
    const float4* xp = (const float4*)(x + n * F_IN);
    #pragma unroll
    for (int v = 0; v < 4; v++) {
        float4 t = xp[v];
        xv[v * 4 + 0] = t.x; xv[v * 4 + 1] = t.y; xv[v * 4 + 2] = t.z; xv[v * 4 + 3] = t.w;
    }

    float q[8];
    #pragma unroll
    for (int f = 0; f < 8; f++) {
        float s = 0.f;
        #pragma unroll
        for (int i = 0; i < F_IN; i++) s = fmaf(xv[i], sW[f * 128 + i * 8 + j], s);
        q[f] = s;
    }
    union { uint4 u; __half2 h[4]; } pk;
    pk.h[0] = __floats2half2_rn(q[0], q[1]);
    pk.h[1] = __floats2half2_rn(q[2], q[3]);
    pk.h[2] = __floats2half2_rn(q[4], q[5]);
    pk.h[3] = __floats2half2_rn(q[6], q[7]);
    *(uint4*)(g_Qh + n * 64 + j * 8) = pk.u;

    float qb = 0.f, r = sb[j];
    #pragma unroll
    for (int i = 0; i < F_IN; i++) {
        qb = fmaf(xv[i], sB[i * 8 + j], qb);
        r  = fmaf(xv[i], sR[i * 8 + j], r);
    }
    g_bias[n * 8 + j] = qb;
    g_agg1[n * 8 + j] = r;
}

// ---------------------------------------------------------------------------
// Layer-2 node precompute: h = relu(agg1); same structure
// ---------------------------------------------------------------------------
__global__ void node2_kernel(const float* __restrict__ We2,
                             const float* __restrict__ be2,
                             const float* __restrict__ root2,
                             const float* __restrict__ b2) {
    __shared__ float sW[F_EDGE * H * H];
    __shared__ float sR[H * H];
    __shared__ float sB[H * H];
    __shared__ float sb[H];
    for (int i = threadIdx.x; i < F_EDGE * H * H; i += blockDim.x) sW[i] = We2[i];
    for (int i = threadIdx.x; i < H * H; i += blockDim.x) { sR[i] = root2[i]; sB[i] = be2[i]; }
    if (threadIdx.x < H) sb[threadIdx.x] = b2[threadIdx.x];
    __syncthreads();

    int gid = blockIdx.x * blockDim.x + threadIdx.x;
    int n = gid >> 3, j = gid & 7;
    if (n >= N_NODES) return;

    float h[H];
    const float4* hp = (const float4*)(g_agg1 + n * 8);
    float4 a0 = hp[0], a1 = hp[1];
    h[0] = fmaxf(a0.x, 0.f); h[1] = fmaxf(a0.y, 0.f);
    h[2] = fmaxf(a0.z, 0.f); h[3] = fmaxf(a0.w, 0.f);
    h[4] = fmaxf(a1.x, 0.f); h[5] = fmaxf(a1.y, 0.f);
    h[6] = fmaxf(a1.z, 0.f); h[7] = fmaxf(a1.w, 0.f);

    float q[8];
    #pragma unroll
    for (int f = 0; f < 8; f++) {
        float s = 0.f;
        #pragma unroll
        for (int i = 0; i < H; i++) s = fmaf(h[i], sW[f * 64 + i * 8 + j], s);
        q[f] = s;
    }
    union { uint4 u; __half2 hh[4]; } pk;
    pk.hh[0] = __floats2half2_rn(q[0], q[1]);
    pk.hh[1] = __floats2half2_rn(q[2], q[3]);
    pk.hh[2] = __floats2half2_rn(q[4], q[5]);
    pk.hh[3] = __floats2half2_rn(q[6], q[7]);
    *(uint4*)(g_Qh + n * 64 + j * 8) = pk.u;

    float qb = 0.f, r = sb[j];
    #pragma unroll
    for (int i = 0; i < H; i++) {
        qb = fmaf(h[i], sB[i * 8 + j], qb);
        r  = fmaf(h[i], sR[i * 8 + j], r);
    }
    g_bias[n * 8 + j] = qb;
    g_agg2[n * 8 + j] = r;
}

// ---------------------------------------------------------------------------
// Gather-aggregate: one 8-lane group per node walks its CSR segment.
// Lane j (channel j): acc += bias[src][j] + sum_f ea16[i,f]*Q[src][j*8+f]
// Register accumulation, ZERO atomics. Software-pipelined 1 deep.
// ---------------------------------------------------------------------------
__global__ void __launch_bounds__(256) agg_kernel(int layer) {
    int gid = blockIdx.x * blockDim.x + threadIdx.x;
    int n = gid >> 3, j = gid & 7;
    if (n >= N_NODES) return;

    int i   = __ldg(&g_rowptr[n]);
    int end = __ldg(&g_rowptr[n + 1]);
    float acc = 0.f;

    int   s  = 0;
    uint4 eu = make_uint4(0, 0, 0, 0), qu = make_uint4(0, 0, 0, 0);
    float qb = 0.f;
    if (i < end) {
        s  = __ldg(&g_src_sorted[i]);
        eu = __ldg((const uint4*)(g_ea16 + (size_t)i * 8));
        qu = __ldg((const uint4*)(g_Qh + s * 64 + j * 8));
        qb = __ldg(&g_bias[s * 8 + j]);
    }
    while (i < end) {
        int i2 = i + 1;
        int   s2 = 0;
        uint4 eu2 = make_uint4(0, 0, 0, 0), qu2 = make_uint4(0, 0, 0, 0);
        float qb2 = 0.f;
        if (i2 < end) {
            s2  = __ldg(&g_src_sorted[i2]);
            eu2 = __ldg((const uint4*)(g_ea16 + (size_t)i2 * 8));
            qu2 = __ldg((const uint4*)(g_Qh + s2 * 64 + j * 8));
            qb2 = __ldg(&g_bias[s2 * 8 + j]);
        }

        union { uint4 u; __half2 h[4]; } ec, qc;
        ec.u = eu; qc.u = qu;
        float2 e0 = __half22float2(ec.h[0]);
        float2 e1 = __half22float2(ec.h[1]);
        float2 e2 = __half22float2(ec.h[2]);
        float2 e3 = __half22float2(ec.h[3]);
        float2 q0 = __half22float2(qc.h[0]);
        float2 q1 = __half22float2(qc.h[1]);
        float2 q2 = __half22float2(qc.h[2]);
        float2 q3 = __half22float2(qc.h[3]);

        acc += qb;
        acc = fmaf(e0.x, q0.x, acc);
        acc = fmaf(e0.y, q0.y, acc);
        acc = fmaf(e1.x, q1.x, acc);
        acc = fmaf(e1.y, q1.y, acc);
        acc = fmaf(e2.x, q2.x, acc);
        acc = fmaf(e2.y, q2.y, acc);
        acc = fmaf(e3.x, q3.x, acc);
        acc = fmaf(e3.y, q3.y, acc);

        i = i2; s = s2; eu = eu2; qu = qu2; qb = qb2;
    }

    float* agg = layer ? g_agg2 : g_agg1;
    agg[n * 8 + j] += acc;   // exclusive owner, plain RMW
}

// ---------------------------------------------------------------------------
// Output init + fused relu / pool / readout with warp-aggregated atomics.
// ---------------------------------------------------------------------------
__global__ void out_init_kernel(const float* __restrict__ blast, float* __restrict__ out) {
    int g = blockIdx.x * blockDim.x + threadIdx.x;
    if (g < NUM_GRAPHS) out[g] = blast[0];
}

__global__ void final_kernel(const int* __restrict__ batch,
                             const float* __restrict__ Wlast,
                             float* __restrict__ out) {
    int n = blockIdx.x * blockDim.x + threadIdx.x;
    bool valid = (n < N_NODES);
    int nc = valid ? n : (N_NODES - 1);

    const float4* ap = (const float4*)(g_agg2 + nc * 8);
    float4 a0 = ap[0], a1 = ap[1];
    float v = 0.f;
    v = fmaf(fmaxf(a0.x, 0.f), __ldg(&Wlast[0]), v);
    v = fmaf(fmaxf(a0.y, 0.f), __ldg(&Wlast[1]), v);
    v = fmaf(fmaxf(a0.z, 0.f), __ldg(&Wlast[2]), v);
    v = fmaf(fmaxf(a0.w, 0.f), __ldg(&Wlast[3]), v);
    v = fmaf(fmaxf(a1.x, 0.f), __ldg(&Wlast[4]), v);
    v = fmaf(fmaxf(a1.y, 0.f), __ldg(&Wlast[5]), v);
    v = fmaf(fmaxf(a1.z, 0.f), __ldg(&Wlast[6]), v);
    v = fmaf(fmaxf(a1.w, 0.f), __ldg(&Wlast[7]), v);
    if (!valid) v = 0.f;

    int b = __ldg(&batch[nc]);
    int b0 = __shfl_sync(0xffffffffu, b, 0);
    if (__all_sync(0xffffffffu, b == b0)) {
        #pragma unroll
        for (int off = 16; off >= 1; off >>= 1)
            v += __shfl_xor_sync(0xffffffffu, v, off, 32);
        if ((threadIdx.x & 31) == 0) atomicAdd(&out[b0], v);
    } else {
        if (valid) atomicAdd(&out[b], v);
    }
}

// ---------------------------------------------------------------------------
extern "C" void kernel_launch(void* const* d_in, const int* in_sizes, int n_in,
                              void* d_out, int out_size) {
    const float* x     = (const float*)d_in[0];
    const int*   ei    = (const int*)  d_in[1];
    const float* ea    = (const float*)d_in[2];
    const int*   batch = (const int*)  d_in[3];
    const float* We1   = (const float*)d_in[4];
    const float* be1   = (const float*)d_in[5];
    const float* root1 = (const float*)d_in[6];
    const float* b1    = (const float*)d_in[7];
    const float* We2   = (const float*)d_in[8];
    const float* be2   = (const float*)d_in[9];
    const float* root2 = (const float*)d_in[10];
    const float* b2    = (const float*)d_in[11];
    const float* Wlast = (const float*)d_in[12];
    const float* blast = (const float*)d_in[13];
    float* out = (float*)d_out;

    const int TPB = 256;
    int node_blocks = (N_NODES * 8 + TPB - 1) / TPB;
    int nodes_tpb   = (N_NODES + TPB - 1) / TPB;
    int edge_tpb    = (N_EDGES + TPB - 1) / TPB;
    int agg_blocks  = (N_NODES * 8 + TPB - 1) / TPB;

    // CSR build (once per launch, reused by both layers)
    zero_cnt_kernel<<<nodes_tpb, TPB>>>();
    hist_kernel<<<edge_tpb, TPB>>>(ei);
    scan1_kernel<<<SCAN_BLKS, SCAN_TPB>>>();
    scan2_kernel<<<1, 128>>>();
    scan3_kernel<<<nodes_tpb, TPB>>>();
    scatter_kernel<<<edge_tpb, TPB>>>(ei, ea);

    node1_kernel<<<node_blocks, TPB>>>(x, We1, be1, root1, b1);
    agg_kernel<<<agg_blocks, TPB>>>(0);
    node2_kernel<<<node_blocks, TPB>>>(We2, be2, root2, b2);
    agg_kernel<<<agg_blocks, TPB>>>(1);
    out_init_kernel<<<(NUM_GRAPHS + TPB - 1) / TPB, TPB>>>(blast, out);
    final_kernel<<<nodes_tpb, TPB>>>(batch, Wlast, out);
}

// round 10
// speedup vs baseline: 1.0785x; 1.0785x over previous
#include <cuda_runtime.h>
#include <cuda_fp16.h>

#define N_NODES   50000
#define N_EDGES   800000
#define F_IN      16
#define F_EDGE    8
#define H         8
#define NUM_GRAPHS 512

// Q (o-major, fp16): Q[n][j*8+f], row = 64 halves = 128 B, line-aligned.
__device__ __align__(128) __half  g_Qh[N_NODES * 64];      // 6.4 MB
__device__ __align__(16)  float   g_bias[N_NODES * H];     // 1.6 MB  (x@Be per node)
// fp32 root terms (written by node kernels)
__device__ __align__(16)  float   g_root1[N_NODES * H];    // 1.6 MB
__device__ __align__(16)  float   g_root2[N_NODES * H];    // 1.6 MB
// fp16 edge-sum accumulators (zeroed each launch; RED.F16x2 targets)
__device__ __align__(16)  __half2 g_aggh1[N_NODES * 4];    // 0.8 MB
__device__ __align__(16)  __half2 g_aggh2[N_NODES * 4];    // 0.8 MB

// ---------------------------------------------------------------------------
// Zero the fp16 accumulators (both layers), 16B stores.
// N_NODES*4 half2 per buffer; one uint4 covers 4 half2 -> N_NODES uint4 each.
// ---------------------------------------------------------------------------
__global__ void zero_aggh_kernel() {
    int i = blockIdx.x * blockDim.x + threadIdx.x;
    const int NV = N_NODES;   // uint4 count per buffer (FIXED: was /8 bug)
    if (i < NV) {
        ((uint4*)g_aggh1)[i] = make_uint4(0, 0, 0, 0);
        ((uint4*)g_aggh2)[i] = make_uint4(0, 0, 0, 0);
    }
}

// ---------------------------------------------------------------------------
// Layer-1 node precompute (8 lanes per node, lane j = output channel j):
//   Qh[n][j*8+f] = sum_i x[n,i]*We1[f, i*8+j]    (fp16, o-major)
//   bias[n][j]   = sum_i x[n,i]*be1[i*8+j]
//   root1[n][j]  = x[n]@root1[:,j] + b1[j]
// ---------------------------------------------------------------------------
__global__ void node1_kernel(const float* __restrict__ x,
                             const float* __restrict__ We1,
                             const float* __restrict__ be1,
                             const float* __restrict__ root1,
                             const float* __restrict__ b1) {
    __shared__ float sW[F_EDGE * F_IN * H];
    __shared__ float sR[F_IN * H];
    __shared__ float sB[F_IN * H];
    __shared__ float sb[H];
    for (int i = threadIdx.x; i < F_EDGE * F_IN * H; i += blockDim.x) sW[i] = We1[i];
    for (int i = threadIdx.x; i < F_IN * H; i += blockDim.x) { sR[i] = root1[i]; sB[i] = be1[i]; }
    if (threadIdx.x < H) sb[threadIdx.x] = b1[threadIdx.x];
    __syncthreads();

    int gid = blockIdx.x * blockDim.x + threadIdx.x;
    int n = gid >> 3, j = gid & 7;
    if (n >= N_NODES) return;

    float xv[F_IN];
    const float4* xp = (const float4*)(x + n * F_IN);
    #pragma unroll
    for (int v = 0; v < 4; v++) {
        float4 t = xp[v];
        xv[v * 4 + 0] = t.x; xv[v * 4 + 1] = t.y; xv[v * 4 + 2] = t.z; xv[v * 4 + 3] = t.w;
    }

    float q[8];
    #pragma unroll
    for (int f = 0; f < 8; f++) {
        float s = 0.f;
        #pragma unroll
        for (int i = 0; i < F_IN; i++) s = fmaf(xv[i], sW[f * 128 + i * 8 + j], s);
        q[f] = s;
    }
    union { uint4 u; __half2 h[4]; } pk;
    pk.h[0] = __floats2half2_rn(q[0], q[1]);
    pk.h[1] = __floats2half2_rn(q[2], q[3]);
    pk.h[2] = __floats2half2_rn(q[4], q[5]);
    pk.h[3] = __floats2half2_rn(q[6], q[7]);
    *(uint4*)(g_Qh + n * 64 + j * 8) = pk.u;

    float qb = 0.f, r = sb[j];
    #pragma unroll
    for (int i = 0; i < F_IN; i++) {
        qb = fmaf(xv[i], sB[i * 8 + j], qb);
        r  = fmaf(xv[i], sR[i * 8 + j], r);
    }
    g_bias[n * 8 + j] = qb;
    g_root1[n * 8 + j] = r;
}

// ---------------------------------------------------------------------------
// Layer-2 node precompute: h = relu(root1 + fp16 edge-sum); same structure.
// ---------------------------------------------------------------------------
__global__ void node2_kernel(const float* __restrict__ We2,
                             const float* __restrict__ be2,
                             const float* __restrict__ root2,
                             const float* __restrict__ b2) {
    __shared__ float sW[F_EDGE * H * H];
    __shared__ float sR[H * H];
    __shared__ float sB[H * H];
    __shared__ float sb[H];
    for (int i = threadIdx.x; i < F_EDGE * H * H; i += blockDim.x) sW[i] = We2[i];
    for (int i = threadIdx.x; i < H * H; i += blockDim.x) { sR[i] = root2[i]; sB[i] = be2[i]; }
    if (threadIdx.x < H) sb[threadIdx.x] = b2[threadIdx.x];
    __syncthreads();

    int gid = blockIdx.x * blockDim.x + threadIdx.x;
    int n = gid >> 3, j = gid & 7;
    if (n >= N_NODES) return;

    const float4* hp = (const float4*)(g_root1 + n * 8);
    float4 a0 = hp[0], a1 = hp[1];
    union { uint4 u; __half2 hh[4]; } ag;
    ag.u = *(const uint4*)(g_aggh1 + n * 4);
    float2 s0 = __half22float2(ag.hh[0]);
    float2 s1 = __half22float2(ag.hh[1]);
    float2 s2 = __half22float2(ag.hh[2]);
    float2 s3 = __half22float2(ag.hh[3]);

    float h[H];
    h[0] = fmaxf(a0.x + s0.x, 0.f); h[1] = fmaxf(a0.y + s0.y, 0.f);
    h[2] = fmaxf(a0.z + s1.x, 0.f); h[3] = fmaxf(a0.w + s1.y, 0.f);
    h[4] = fmaxf(a1.x + s2.x, 0.f); h[5] = fmaxf(a1.y + s2.y, 0.f);
    h[6] = fmaxf(a1.z + s3.x, 0.f); h[7] = fmaxf(a1.w + s3.y, 0.f);

    float q[8];
    #pragma unroll
    for (int f = 0; f < 8; f++) {
        float s = 0.f;
        #pragma unroll
        for (int i = 0; i < H; i++) s = fmaf(h[i], sW[f * 64 + i * 8 + j], s);
        q[f] = s;
    }
    union { uint4 u; __half2 hh[4]; } pk;
    pk.hh[0] = __floats2half2_rn(q[0], q[1]);
    pk.hh[1] = __floats2half2_rn(q[2], q[3]);
    pk.hh[2] = __floats2half2_rn(q[4], q[5]);
    pk.hh[3] = __floats2half2_rn(q[6], q[7]);
    *(uint4*)(g_Qh + n * 64 + j * 8) = pk.u;

    float qb = 0.f, r = sb[j];
    #pragma unroll
    for (int i = 0; i < H; i++) {
        qb = fmaf(h[i], sB[i * 8 + j], qb);
        r  = fmaf(h[i], sR[i * 8 + j], r);
    }
    g_bias[n * 8 + j] = qb;
    g_root2[n * 8 + j] = r;
}

// ---------------------------------------------------------------------------
// Edge pass: 4 lanes per edge, lane h owns channels 2h and 2h+1.
//   r0 = bias[src][2h]   + sum_f ea[e,f]*Q[src][(2h)*8+f]
//   r1 = bias[src][2h+1] + sum_f ea[e,f]*Q[src][(2h+1)*8+f]
//   ONE atomicAdd(__half2*) per lane -> red elements halved (3.2M/pass).
// Group of 4 lanes still covers one 128B Q line; no shuffles, no divergence.
// ---------------------------------------------------------------------------
#define EPT 2
#define HALF_E (N_EDGES / EPT)

__global__ void __launch_bounds__(256) edge_kernel(const int* __restrict__ ei,
                                                   const float* __restrict__ ea,
                                                   int layer) {
    int gid = blockIdx.x * blockDim.x + threadIdx.x;
    int e0 = gid >> 2, h = gid & 3;
    __half2* aggh = layer ? g_aggh2 : g_aggh1;

    #pragma unroll
    for (int k = 0; k < EPT; k++) {
        int e = e0 + k * HALF_E;
        int s = __ldg(&ei[e]);
        int d = __ldg(&ei[N_EDGES + e]);

        const float4* eap = (const float4*)(ea + e * 8);
        float4 a0 = __ldg(eap);
        float4 a1 = __ldg(eap + 1);

        const uint4* qp = (const uint4*)(g_Qh + s * 64 + h * 16);
        uint4 qA = __ldg(qp);       // channel 2h
        uint4 qB = __ldg(qp + 1);   // channel 2h+1
        float2 bb = __ldg((const float2*)(g_bias + s * 8 + h * 2));

        union { uint4 u; __half2 hh[4]; } ca, cb;
        ca.u = qA; cb.u = qB;
        float2 p0 = __half22float2(ca.hh[0]);
        float2 p1 = __half22float2(ca.hh[1]);
        float2 p2 = __half22float2(ca.hh[2]);
        float2 p3 = __half22float2(ca.hh[3]);
        float2 u0 = __half22float2(cb.hh[0]);
        float2 u1 = __half22float2(cb.hh[1]);
        float2 u2 = __half22float2(cb.hh[2]);
        float2 u3 = __half22float2(cb.hh[3]);

        float r0 = bb.x, r1 = bb.y;
        r0 = fmaf(a0.x, p0.x, r0); r1 = fmaf(a0.x, u0.x, r1);
        r0 = fmaf(a0.y, p0.y, r0); r1 = fmaf(a0.y, u0.y, r1);
        r0 = fmaf(a0.z, p1.x, r0); r1 = fmaf(a0.z, u1.x, r1);
        r0 = fmaf(a0.w, p1.y, r0); r1 = fmaf(a0.w, u1.y, r1);
        r0 = fmaf(a1.x, p2.x, r0); r1 = fmaf(a1.x, u2.x, r1);
        r0 = fmaf(a1.y, p2.y, r0); r1 = fmaf(a1.y, u2.y, r1);
        r0 = fmaf(a1.z, p3.x, r0); r1 = fmaf(a1.z, u3.x, r1);
        r0 = fmaf(a1.w, p3.y, r0); r1 = fmaf(a1.w, u3.y, r1);

        atomicAdd(&aggh[d * 4 + h], __floats2half2_rn(r0, r1));
    }
}

// ---------------------------------------------------------------------------
// Output init + fused relu / pool / readout with warp-aggregated atomics.
// ---------------------------------------------------------------------------
__global__ void out_init_kernel(const float* __restrict__ blast, float* __restrict__ out) {
    int g = blockIdx.x * blockDim.x + threadIdx.x;
    if (g < NUM_GRAPHS) out[g] = blast[0];
}

__global__ void final_kernel(const int* __restrict__ batch,
                             const float* __restrict__ Wlast,
                             float* __restrict__ out) {
    int n = blockIdx.x * blockDim.x + threadIdx.x;
    bool valid = (n < N_NODES);
    int nc = valid ? n : (N_NODES - 1);

    const float4* ap = (const float4*)(g_root2 + nc * 8);
    float4 a0 = ap[0], a1 = ap[1];
    union { uint4 u; __half2 hh[4]; } ag;
    ag.u = *(const uint4*)(g_aggh2 + nc * 4);
    float2 s0 = __half22float2(ag.hh[0]);
    float2 s1 = __half22float2(ag.hh[1]);
    float2 s2 = __half22float2(ag.hh[2]);
    float2 s3 = __half22float2(ag.hh[3]);

    float v = 0.f;
    v = fmaf(fmaxf(a0.x + s0.x, 0.f), __ldg(&Wlast[0]), v);
    v = fmaf(fmaxf(a0.y + s0.y, 0.f), __ldg(&Wlast[1]), v);
    v = fmaf(fmaxf(a0.z + s1.x, 0.f), __ldg(&Wlast[2]), v);
    v = fmaf(fmaxf(a0.w + s1.y, 0.f), __ldg(&Wlast[3]), v);
    v = fmaf(fmaxf(a1.x + s2.x, 0.f), __ldg(&Wlast[4]), v);
    v = fmaf(fmaxf(a1.y + s2.y, 0.f), __ldg(&Wlast[5]), v);
    v = fmaf(fmaxf(a1.z + s3.x, 0.f), __ldg(&Wlast[6]), v);
    v = fmaf(fmaxf(a1.w + s3.y, 0.f), __ldg(&Wlast[7]), v);
    if (!valid) v = 0.f;

    int b = __ldg(&batch[nc]);
    int b0 = __shfl_sync(0xffffffffu, b, 0);
    if (__all_sync(0xffffffffu, b == b0)) {
        #pragma unroll
        for (int off = 16; off >= 1; off >>= 1)
            v += __shfl_xor_sync(0xffffffffu, v, off, 32);
        if ((threadIdx.x & 31) == 0) atomicAdd(&out[b0], v);
    } else {
        if (valid) atomicAdd(&out[b], v);
    }
}

// ---------------------------------------------------------------------------
extern "C" void kernel_launch(void* const* d_in, const int* in_sizes, int n_in,
                              void* d_out, int out_size) {
    const float* x     = (const float*)d_in[0];
    const int*   ei    = (const int*)  d_in[1];
    const float* ea    = (const float*)d_in[2];
    const int*   batch = (const int*)  d_in[3];
    const float* We1   = (const float*)d_in[4];
    const float* be1   = (const float*)d_in[5];
    const float* root1 = (const float*)d_in[6];
    const float* b1    = (const float*)d_in[7];
    const float* We2   = (const float*)d_in[8];
    const float* be2   = (const float*)d_in[9];
    const float* root2 = (const float*)d_in[10];
    const float* b2    = (const float*)d_in[11];
    const float* Wlast = (const float*)d_in[12];
    const float* blast = (const float*)d_in[13];
    float* out = (float*)d_out;

    const int TPB = 256;
    int node_blocks = (N_NODES * 8 + TPB - 1) / TPB;
    int edge_blocks = (HALF_E * 4) / TPB;           // 6250, exact
    int fin_blocks  = (N_NODES + TPB - 1) / TPB;
    int zero_blocks = (N_NODES + TPB - 1) / TPB;    // N_NODES uint4 per buffer

    zero_aggh_kernel<<<zero_blocks, TPB>>>();
    node1_kernel<<<node_blocks, TPB>>>(x, We1, be1, root1, b1);
    edge_kernel<<<edge_blocks, TPB>>>(ei, ea, 0);
    node2_kernel<<<node_blocks, TPB>>>(We2, be2, root2, b2);
    edge_kernel<<<edge_blocks, TPB>>>(ei, ea, 1);
    out_init_kernel<<<(NUM_GRAPHS + TPB - 1) / TPB, TPB>>>(blast, out);
    final_kernel<<<fin_blocks, TPB>>>(batch, Wlast, out);
}

// round 12
// speedup vs baseline: 1.7032x; 1.5793x over previous
#include <cuda_runtime.h>
#include <cuda_fp16.h>

#define N_NODES   50000
#define N_EDGES   800000
#define F_IN      16
#define F_EDGE    8
#define H         8
#define NUM_GRAPHS 512

// Q (o-major, fp16): Q[n][j*8+f], row = 64 halves = 128 B, line-aligned.
__device__ __align__(128) __half g_Qh[N_NODES * 64];       // 6.4 MB
__device__ __align__(16)  float  g_bias[N_NODES * H];      // 1.6 MB  (x@Be per node)
__device__ __align__(16)  float  g_agg1[N_NODES * H];      // 1.6 MB
__device__ __align__(16)  float  g_agg2[N_NODES * H];      // 1.6 MB

// ---------------------------------------------------------------------------
// Layer-1 node precompute (8 lanes per node, lane j = output channel j):
//   Qh[n][j*8+f] = sum_i x[n,i]*We1[f, i*8+j]    (fp16, o-major)
//   bias[n][j]   = sum_i x[n,i]*be1[i*8+j]
//   agg1[n][j]   = x[n]@root1[:,j] + b1[j]       (edge atomics add onto this)
// ---------------------------------------------------------------------------
__global__ void node1_kernel(const float* __restrict__ x,
                             const float* __restrict__ We1,
                             const float* __restrict__ be1,
                             const float* __restrict__ root1,
                             const float* __restrict__ b1) {
    __shared__ float sW[F_EDGE * F_IN * H];
    __shared__ float sR[F_IN * H];
    __shared__ float sB[F_IN * H];
    __shared__ float sb[H];
    for (int i = threadIdx.x; i < F_EDGE * F_IN * H; i += blockDim.x) sW[i] = We1[i];
    for (int i = threadIdx.x; i < F_IN * H; i += blockDim.x) { sR[i] = root1[i]; sB[i] = be1[i]; }
    if (threadIdx.x < H) sb[threadIdx.x] = b1[threadIdx.x];
    __syncthreads();

    int gid = blockIdx.x * blockDim.x + threadIdx.x;
    int n = gid >> 3, j = gid & 7;
    if (n >= N_NODES) return;

    float xv[F_IN];
    const float4* xp = (const float4*)(x + n * F_IN);
    #pragma unroll
    for (int v = 0; v < 4; v++) {
        float4 t = xp[v];
        xv[v * 4 + 0] = t.x; xv[v * 4 + 1] = t.y; xv[v * 4 + 2] = t.z; xv[v * 4 + 3] = t.w;
    }

    float q[8];
    #pragma unroll
    for (int f = 0; f < 8; f++) {
        float s = 0.f;
        #pragma unroll
        for (int i = 0; i < F_IN; i++) s = fmaf(xv[i], sW[f * 128 + i * 8 + j], s);
        q[f] = s;
    }
    union { uint4 u; __half2 h[4]; } pk;
    pk.h[0] = __floats2half2_rn(q[0], q[1]);
    pk.h[1] = __floats2half2_rn(q[2], q[3]);
    pk.h[2] = __floats2half2_rn(q[4], q[5]);
    pk.h[3] = __floats2half2_rn(q[6], q[7]);
    *(uint4*)(g_Qh + n * 64 + j * 8) = pk.u;

    float qb = 0.f, r = sb[j];
    #pragma unroll
    for (int i = 0; i < F_IN; i++) {
        qb = fmaf(xv[i], sB[i * 8 + j], qb);
        r  = fmaf(xv[i], sR[i * 8 + j], r);
    }
    g_bias[n * 8 + j] = qb;
    g_agg1[n * 8 + j] = r;
}

// ---------------------------------------------------------------------------
// Layer-2 node precompute: h = relu(agg1); same structure
// ---------------------------------------------------------------------------
__global__ void node2_kernel(const float* __restrict__ We2,
                             const float* __restrict__ be2,
                             const float* __restrict__ root2,
                             const float* __restrict__ b2) {
    __shared__ float sW[F_EDGE * H * H];
    __shared__ float sR[H * H];
    __shared__ float sB[H * H];
    __shared__ float sb[H];
    for (int i = threadIdx.x; i < F_EDGE * H * H; i += blockDim.x) sW[i] = We2[i];
    for (int i = threadIdx.x; i < H * H; i += blockDim.x) { sR[i] = root2[i]; sB[i] = be2[i]; }
    if (threadIdx.x < H) sb[threadIdx.x] = b2[threadIdx.x];
    __syncthreads();

    int gid = blockIdx.x * blockDim.x + threadIdx.x;
    int n = gid >> 3, j = gid & 7;
    if (n >= N_NODES) return;

    float h[H];
    const float4* hp = (const float4*)(g_agg1 + n * 8);
    float4 a0 = hp[0], a1 = hp[1];
    h[0] = fmaxf(a0.x, 0.f); h[1] = fmaxf(a0.y, 0.f);
    h[2] = fmaxf(a0.z, 0.f); h[3] = fmaxf(a0.w, 0.f);
    h[4] = fmaxf(a1.x, 0.f); h[5] = fmaxf(a1.y, 0.f);
    h[6] = fmaxf(a1.z, 0.f); h[7] = fmaxf(a1.w, 0.f);

    float q[8];
    #pragma unroll
    for (int f = 0; f < 8; f++) {
        float s = 0.f;
        #pragma unroll
        for (int i = 0; i < H; i++) s = fmaf(h[i], sW[f * 64 + i * 8 + j], s);
        q[f] = s;
    }
    union { uint4 u; __half2 hh[4]; } pk;
    pk.hh[0] = __floats2half2_rn(q[0], q[1]);
    pk.hh[1] = __floats2half2_rn(q[2], q[3]);
    pk.hh[2] = __floats2half2_rn(q[4], q[5]);
    pk.hh[3] = __floats2half2_rn(q[6], q[7]);
    *(uint4*)(g_Qh + n * 64 + j * 8) = pk.u;

    float qb = 0.f, r = sb[j];
    #pragma unroll
    for (int i = 0; i < H; i++) {
        qb = fmaf(h[i], sB[i * 8 + j], qb);
        r  = fmaf(h[i], sR[i * 8 + j], r);
    }
    g_bias[n * 8 + j] = qb;
    g_agg2[n * 8 + j] = r;
}

// ---------------------------------------------------------------------------
// Edge pass (R4-proven): 8 lanes per edge, 2 edges per thread, fp16 Q,
// scalar fp32 atomicAdd. Layer is a template arg (agg pointer immediate).
// ---------------------------------------------------------------------------
#define EPT 2
#define HALF_E (N_EDGES / EPT)

template <int LAYER>
__global__ void __launch_bounds__(256) edge_kernel(const int* __restrict__ ei,
                                                   const float* __restrict__ ea) {
    int gid = blockIdx.x * blockDim.x + threadIdx.x;
    int e0 = gid >> 3, j = gid & 7;
    float* agg = LAYER ? g_agg2 : g_agg1;

    #pragma unroll
    for (int k = 0; k < EPT; k++) {
        int e = e0 + k * HALF_E;
        int s = __ldg(&ei[e]);
        int d = __ldg(&ei[N_EDGES + e]);

        const float4* eap = (const float4*)(ea + e * 8);
        float4 a0 = __ldg(eap);
        float4 a1 = __ldg(eap + 1);

        uint4 qraw = __ldg((const uint4*)(g_Qh + s * 64 + j * 8));
        union { uint4 u; __half2 h[4]; } qk; qk.u = qraw;
        float2 f0 = __half22float2(qk.h[0]);
        float2 f1 = __half22float2(qk.h[1]);
        float2 f2 = __half22float2(qk.h[2]);
        float2 f3 = __half22float2(qk.h[3]);

        float r = __ldg(&g_bias[s * 8 + j]);
        r = fmaf(a0.x, f0.x, r);
        r = fmaf(a0.y, f0.y, r);
        r = fmaf(a0.z, f1.x, r);
        r = fmaf(a0.w, f1.y, r);
        r = fmaf(a1.x, f2.x, r);
        r = fmaf(a1.y, f2.y, r);
        r = fmaf(a1.z, f3.x, r);
        r = fmaf(a1.w, f3.y, r);

        atomicAdd(&agg[d * 8 + j], r);
    }
}

// ---------------------------------------------------------------------------
// Fused pool + readout, NO atomics, NO init kernel.
// batch is sorted: block g binary-searches its contiguous node range
// [lower_bound(g), lower_bound(g+1)), sums relu(agg2)@Wlast over it,
// block-reduces, writes out[g] = sum + blast.
// ---------------------------------------------------------------------------
#define FIN_TPB 128

__device__ __forceinline__ int lower_bound_batch(const int* __restrict__ batch, int key) {
    int lo = 0, hi = N_NODES;
    while (lo < hi) {
        int mid = (lo + hi) >> 1;
        if (__ldg(&batch[mid]) < key) lo = mid + 1;
        else hi = mid;
    }
    return lo;
}

__global__ void __launch_bounds__(FIN_TPB) final_kernel(const int* __restrict__ batch,
                                                        const float* __restrict__ Wlast,
                                                        const float* __restrict__ blast,
                                                        float* __restrict__ out) {
    int g = blockIdx.x;
    __shared__ int s_range[2];
    __shared__ float s_warp[FIN_TPB / 32];

    if (threadIdx.x == 0)      s_range[0] = lower_bound_batch(batch, g);
    else if (threadIdx.x == 32) s_range[1] = lower_bound_batch(batch, g + 1);
    __syncthreads();
    int start = s_range[0], end = s_range[1];

    float w[8];
    #pragma unroll
    for (int c = 0; c < 8; c++) w[c] = __ldg(&Wlast[c]);

    float v = 0.f;
    for (int n = start + threadIdx.x; n < end; n += FIN_TPB) {
        const float4* ap = (const float4*)(g_agg2 + n * 8);
        float4 a0 = ap[0], a1 = ap[1];
        v = fmaf(fmaxf(a0.x, 0.f), w[0], v);
        v = fmaf(fmaxf(a0.y, 0.f), w[1], v);
        v = fmaf(fmaxf(a0.z, 0.f), w[2], v);
        v = fmaf(fmaxf(a0.w, 0.f), w[3], v);
        v = fmaf(fmaxf(a1.x, 0.f), w[4], v);
        v = fmaf(fmaxf(a1.y, 0.f), w[5], v);
        v = fmaf(fmaxf(a1.z, 0.f), w[6], v);
        v = fmaf(fmaxf(a1.w, 0.f), w[7], v);
    }

    // block reduce
    #pragma unroll
    for (int off = 16; off >= 1; off >>= 1)
        v += __shfl_xor_sync(0xffffffffu, v, off, 32);
    if ((threadIdx.x & 31) == 0) s_warp[threadIdx.x >> 5] = v;
    __syncthreads();
    if (threadIdx.x == 0) {
        float t = 0.f;
        #pragma unroll
        for (int wi = 0; wi < FIN_TPB / 32; wi++) t += s_warp[wi];
        out[g] = t + __ldg(&blast[0]);
    }
}

// ---------------------------------------------------------------------------
extern "C" void kernel_launch(void* const* d_in, const int* in_sizes, int n_in,
                              void* d_out, int out_size) {
    const float* x     = (const float*)d_in[0];
    const int*   ei    = (const int*)  d_in[1];
    const float* ea    = (const float*)d_in[2];
    const int*   batch = (const int*)  d_in[3];
    const float* We1   = (const float*)d_in[4];
    const float* be1   = (const float*)d_in[5];
    const float* root1 = (const float*)d_in[6];
    const float* b1    = (const float*)d_in[7];
    const float* We2   = (const float*)d_in[8];
    const float* be2   = (const float*)d_in[9];
    const float* root2 = (const float*)d_in[10];
    const float* b2    = (const float*)d_in[11];
    const float* Wlast = (const float*)d_in[12];
    const float* blast = (const float*)d_in[13];
    float* out = (float*)d_out;

    const int TPB = 256;
    int node_blocks = (N_NODES * 8 + TPB - 1) / TPB;
    int edge_blocks = (HALF_E * 8) / TPB;           // 12500, exact

    node1_kernel<<<node_blocks, TPB>>>(x, We1, be1, root1, b1);
    edge_kernel<0><<<edge_blocks, TPB>>>(ei, ea);
    node2_kernel<<<node_blocks, TPB>>>(We2, be2, root2, b2);
    edge_kernel<1><<<edge_blocks, TPB>>>(ei, ea);
    final_kernel<<<NUM_GRAPHS, FIN_TPB>>>(batch, Wlast, blast, out);
}